// round 2
// baseline (speedup 1.0000x reference)
#include <cuda_runtime.h>

// GCN_75050258530542 — round 2: counting-sort by dst, then register-resident
// gather-reduce (no feature atomics).
// out[n,64] = norm_d[n] * (sum_{e: dst[e]==n} x[src[e],15:25]*norm_s[src[e]]) @ (W1@W2)
//             + (b1@W2 + b2)

constexpr int NMAX = 100000;
constexpr int EMAX = 3200000;
constexpr int FP   = 12;   // 10 features padded to 12 floats (48B rows); pad stays 0

__device__ int   g_deg_out[NMAX];
__device__ int   g_deg_in[NMAX];
__device__ int   g_off[NMAX];
__device__ int   g_cursor[NMAX];
__device__ int   g_esrc[EMAX];                       // src ids binned by dst
__device__ __align__(16) float g_xsn[NMAX * FP];     // x[:,15:25] * norm_s
__device__ __align__(16) float g_agg[NMAX * FP];
__device__ float g_normd[NMAX];
__device__ float g_Weff[640];                        // W1@W2  (10 x 64)
__device__ float g_beff[64];                         // b1@W2 + b2

// ---------------------------------------------------------------- zero counters
__global__ void k_zero(int N) {
    int i = blockIdx.x * blockDim.x + threadIdx.x;
    int stride = gridDim.x * blockDim.x;
    for (int k = i; k < N; k += stride) { g_deg_out[k] = 0; g_deg_in[k] = 0; }
}

// ---------------------------------------------------------------- degrees (int)
__global__ void k_degree(const int* __restrict__ src, const int* __restrict__ dst, int E) {
    int t = blockIdx.x * blockDim.x + threadIdx.x;
    int nq = E >> 2;
    if (t < nq) {
        int4 s = reinterpret_cast<const int4*>(src)[t];
        int4 d = reinterpret_cast<const int4*>(dst)[t];
        atomicAdd(&g_deg_out[s.x], 1);
        atomicAdd(&g_deg_out[s.y], 1);
        atomicAdd(&g_deg_out[s.z], 1);
        atomicAdd(&g_deg_out[s.w], 1);
        atomicAdd(&g_deg_in[d.x], 1);
        atomicAdd(&g_deg_in[d.y], 1);
        atomicAdd(&g_deg_in[d.z], 1);
        atomicAdd(&g_deg_in[d.w], 1);
    }
    if (t == 0) {
        for (int e = (nq << 2); e < E; e++) {
            atomicAdd(&g_deg_out[src[e]], 1);
            atomicAdd(&g_deg_in[dst[e]], 1);
        }
    }
}

// ---------------------------------------------------------------- exclusive scan of deg_in (1 block)
__global__ void k_scan(int N) {
    __shared__ int part[1024];
    int t = threadIdx.x;
    int chunk = (N + 1023) >> 10;
    int beg = t * chunk;
    int end = beg + chunk; if (end > N) end = N;
    int s = 0;
    for (int i = beg; i < end; i++) s += g_deg_in[i];
    part[t] = s;
    __syncthreads();
    // Hillis-Steele inclusive scan
    for (int d = 1; d < 1024; d <<= 1) {
        int u = (t >= d) ? part[t - d] : 0;
        __syncthreads();
        part[t] += u;
        __syncthreads();
    }
    int run = part[t] - s;   // exclusive prefix for this chunk
    for (int i = beg; i < end; i++) {
        g_off[i] = run;
        g_cursor[i] = run;
        run += g_deg_in[i];
    }
}

// ---------------------------------------------------------------- per-node prep
__global__ void k_prep(const float* __restrict__ x, int N) {
    int i = blockIdx.x * blockDim.x + threadIdx.x;
    if (i >= N) return;
    int dout = g_deg_out[i];
    int din  = g_deg_in[i];
    float ns = rsqrtf(dout > 0 ? (float)dout : 1.f);
    float nd = rsqrtf(din  > 0 ? (float)din  : 1.f);
    g_normd[i] = nd;
    const float* xr = x + (size_t)i * 40 + 15;
    float* o = g_xsn + i * FP;
#pragma unroll
    for (int k = 0; k < 10; k++) o[k] = xr[k] * ns;
    // o[10], o[11] remain zero (device globals zero-init, never written)
}

// ---------------------------------------------------------------- bin edges by dst
__global__ void k_bin(const int* __restrict__ src, const int* __restrict__ dst, int E) {
    int t = blockIdx.x * blockDim.x + threadIdx.x;
    int nq = E >> 2;
    if (t < nq) {
        int4 s = reinterpret_cast<const int4*>(src)[t];
        int4 d = reinterpret_cast<const int4*>(dst)[t];
        int p0 = atomicAdd(&g_cursor[d.x], 1);
        int p1 = atomicAdd(&g_cursor[d.y], 1);
        int p2 = atomicAdd(&g_cursor[d.z], 1);
        int p3 = atomicAdd(&g_cursor[d.w], 1);
        g_esrc[p0] = s.x;
        g_esrc[p1] = s.y;
        g_esrc[p2] = s.z;
        g_esrc[p3] = s.w;
    }
    if (t == 0) {
        for (int e = (nq << 2); e < E; e++) {
            int p = atomicAdd(&g_cursor[dst[e]], 1);
            g_esrc[p] = src[e];
        }
    }
}

// ---------------------------------------------------------------- gather-reduce per node
__global__ void k_gather(int N) {
    int n = blockIdx.x * blockDim.x + threadIdx.x;
    if (n >= N) return;
    int beg = g_off[n];
    int cnt = g_deg_in[n];
    float4 acc0 = {0.f, 0.f, 0.f, 0.f};
    float4 acc1 = {0.f, 0.f, 0.f, 0.f};
    float4 acc2 = {0.f, 0.f, 0.f, 0.f};
    int i = 0;
    for (; i + 4 <= cnt; i += 4) {
        int s0 = __ldg(&g_esrc[beg + i + 0]);
        int s1 = __ldg(&g_esrc[beg + i + 1]);
        int s2 = __ldg(&g_esrc[beg + i + 2]);
        int s3 = __ldg(&g_esrc[beg + i + 3]);
        const float4* r0 = reinterpret_cast<const float4*>(g_xsn + s0 * FP);
        const float4* r1 = reinterpret_cast<const float4*>(g_xsn + s1 * FP);
        const float4* r2 = reinterpret_cast<const float4*>(g_xsn + s2 * FP);
        const float4* r3 = reinterpret_cast<const float4*>(g_xsn + s3 * FP);
        float4 a0 = r0[0], b0 = r0[1], c0 = r0[2];
        float4 a1 = r1[0], b1 = r1[1], c1 = r1[2];
        float4 a2 = r2[0], b2 = r2[1], c2 = r2[2];
        float4 a3 = r3[0], b3 = r3[1], c3 = r3[2];
        acc0.x += a0.x + a1.x + a2.x + a3.x;
        acc0.y += a0.y + a1.y + a2.y + a3.y;
        acc0.z += a0.z + a1.z + a2.z + a3.z;
        acc0.w += a0.w + a1.w + a2.w + a3.w;
        acc1.x += b0.x + b1.x + b2.x + b3.x;
        acc1.y += b0.y + b1.y + b2.y + b3.y;
        acc1.z += b0.z + b1.z + b2.z + b3.z;
        acc1.w += b0.w + b1.w + b2.w + b3.w;
        acc2.x += c0.x + c1.x + c2.x + c3.x;
        acc2.y += c0.y + c1.y + c2.y + c3.y;
        acc2.z += c0.z + c1.z + c2.z + c3.z;
        acc2.w += c0.w + c1.w + c2.w + c3.w;
    }
    for (; i < cnt; i++) {
        int s = __ldg(&g_esrc[beg + i]);
        const float4* r = reinterpret_cast<const float4*>(g_xsn + s * FP);
        float4 a = r[0], b = r[1], c = r[2];
        acc0.x += a.x; acc0.y += a.y; acc0.z += a.z; acc0.w += a.w;
        acc1.x += b.x; acc1.y += b.y; acc1.z += b.z; acc1.w += b.w;
        acc2.x += c.x; acc2.y += c.y; acc2.z += c.z; acc2.w += c.w;
    }
    float nd = g_normd[n];
    acc0.x *= nd; acc0.y *= nd; acc0.z *= nd; acc0.w *= nd;
    acc1.x *= nd; acc1.y *= nd; acc1.z *= nd; acc1.w *= nd;
    acc2.x *= nd; acc2.y *= nd;
    acc2.z = 0.f; acc2.w = 0.f;
    float4* o = reinterpret_cast<float4*>(g_agg + n * FP);
    o[0] = acc0; o[1] = acc1; o[2] = acc2;
}

// ---------------------------------------------------------------- fold MLP
__global__ void k_weff(const float* __restrict__ W1, const float* __restrict__ b1,
                       const float* __restrict__ W2, const float* __restrict__ b2) {
    int t = threadIdx.x;
    if (t < 640) {
        int i = t >> 6, j = t & 63;
        float s = 0.f;
#pragma unroll 8
        for (int k = 0; k < 128; k++) s += W1[i * 128 + k] * W2[k * 64 + j];
        g_Weff[t] = s;
    } else if (t < 704) {
        int j = t - 640;
        float s = b2[j];
#pragma unroll 8
        for (int k = 0; k < 128; k++) s += b1[k] * W2[k * 64 + j];
        g_beff[j] = s;
    }
}

// ---------------------------------------------------------------- output matvec (norm already applied)
__global__ void k_out(float* __restrict__ out, int N) {
    __shared__ float sW[640];
    __shared__ float sb[64];
    int t = threadIdx.x;
    for (int k = t; k < 640; k += 256) sW[k] = g_Weff[k];
    if (t < 64) sb[t] = g_beff[t];
    __syncthreads();
    int node = blockIdx.x * 4 + (t >> 6);
    if (node >= N) return;
    int j = t & 63;
    const float* ar = g_agg + node * FP;
    float4 a0 = *reinterpret_cast<const float4*>(ar);
    float4 a1 = *reinterpret_cast<const float4*>(ar + 4);
    float2 a2 = *reinterpret_cast<const float2*>(ar + 8);
    float a[10] = {a0.x, a0.y, a0.z, a0.w, a1.x, a1.y, a1.z, a1.w, a2.x, a2.y};
    float acc = sb[j];
#pragma unroll
    for (int k = 0; k < 10; k++) acc += a[k] * sW[k * 64 + j];
    out[(size_t)node * 64 + j] = acc;
}

// ---------------------------------------------------------------- launch
extern "C" void kernel_launch(void* const* d_in, const int* in_sizes, int n_in,
                              void* d_out, int out_size) {
    const float* x   = (const float*)d_in[0];
    const int*   src = (const int*)d_in[1];
    const int*   dst = (const int*)d_in[2];
    const float* W1  = (const float*)d_in[3];
    const float* b1  = (const float*)d_in[4];
    const float* W2  = (const float*)d_in[5];
    const float* b2  = (const float*)d_in[6];
    float* out = (float*)d_out;

    int N = in_sizes[0] / 40;
    int E = in_sizes[1];
    int nq = E >> 2;
    int eb = nq > 0 ? (nq + 255) / 256 : 1;

    k_zero<<<256, 256>>>(N);
    k_weff<<<1, 704>>>(W1, b1, W2, b2);
    k_degree<<<eb, 256>>>(src, dst, E);
    k_scan<<<1, 1024>>>(N);
    k_prep<<<(N + 255) / 256, 256>>>(x, N);
    k_bin<<<eb, 256>>>(src, dst, E);
    k_gather<<<(N + 127) / 128, 128>>>(N);
    k_out<<<(N + 3) / 4, 256>>>(out, N);
}

// round 3
// speedup vs baseline: 2.0122x; 2.0122x over previous
#include <cuda_runtime.h>

// GCN_75050258530542 — round 3: CSR counting-sort with parallel scan,
// warp-per-node gather fused with the (W1@W2) matvec output.
// out[n,:] = rsqrt(deg_in[n]) * (sum_{e:dst=n} x[src,15:25]*rsqrt(deg_out[src])) @ Weff + beff

constexpr int NMAX = 100000;
constexpr int EMAX = 3200000;
constexpr int FP   = 12;     // padded feature row (48B); pad stays 0 (never written)
constexpr int SB   = 256;    // scan block size

__device__ int   g_deg_out[NMAX];
__device__ int   g_deg_in[NMAX];
__device__ int   g_off[NMAX];      // CSR start
__device__ int   g_cursor[NMAX];   // after bin: CSR end
__device__ int   g_bsum[512];
__device__ int   g_bpre[512];
__device__ int   g_esrc[EMAX];     // src ids binned by dst
__device__ __align__(16) float g_xsn[NMAX * FP];   // x[:,15:25] * norm_s
__device__ float g_Weff[640];      // W1@W2 (10 x 64)
__device__ float g_beff[64];       // b1@W2 + b2

// ---------------------------------------------------------------- zero counters
__global__ void k_zero(int N) {
    int i = blockIdx.x * blockDim.x + threadIdx.x;
    int stride = gridDim.x * blockDim.x;
    for (int k = i; k < N; k += stride) { g_deg_out[k] = 0; g_deg_in[k] = 0; }
}

// ---------------------------------------------------------------- degrees
__global__ void k_degree(const int* __restrict__ src, const int* __restrict__ dst, int E) {
    int t = blockIdx.x * blockDim.x + threadIdx.x;
    int nq = E >> 2;
    if (t < nq) {
        int4 s = reinterpret_cast<const int4*>(src)[t];
        int4 d = reinterpret_cast<const int4*>(dst)[t];
        atomicAdd(&g_deg_out[s.x], 1);
        atomicAdd(&g_deg_out[s.y], 1);
        atomicAdd(&g_deg_out[s.z], 1);
        atomicAdd(&g_deg_out[s.w], 1);
        atomicAdd(&g_deg_in[d.x], 1);
        atomicAdd(&g_deg_in[d.y], 1);
        atomicAdd(&g_deg_in[d.z], 1);
        atomicAdd(&g_deg_in[d.w], 1);
    }
    if (t == 0) {
        for (int e = (nq << 2); e < E; e++) {
            atomicAdd(&g_deg_out[src[e]], 1);
            atomicAdd(&g_deg_in[dst[e]], 1);
        }
    }
}

// ---------------------------------------------------------------- scan stage 1: per-block sums
__global__ void k_scan1(int N) {
    __shared__ int s[SB];
    int t = threadIdx.x;
    int i = blockIdx.x * SB + t;
    s[t] = (i < N) ? g_deg_in[i] : 0;
    __syncthreads();
    for (int d = SB >> 1; d > 0; d >>= 1) {
        if (t < d) s[t] += s[t + d];
        __syncthreads();
    }
    if (t == 0) g_bsum[blockIdx.x] = s[0];
}

// ---------------------------------------------------------------- scan stage 2: scan block sums (1 block, 512 thr)
__global__ void k_scan2(int NB) {
    __shared__ int s[512];
    int t = threadIdx.x;
    int v = (t < NB) ? g_bsum[t] : 0;
    s[t] = v;
    __syncthreads();
    for (int d = 1; d < 512; d <<= 1) {
        int u = (t >= d) ? s[t - d] : 0;
        __syncthreads();
        s[t] += u;
        __syncthreads();
    }
    g_bpre[t] = s[t] - v;   // exclusive prefix of block sums
}

// ---------------------------------------------------------------- scan stage 3: block-local scan + base
__global__ void k_scan3(int N) {
    __shared__ int s[SB];
    int t = threadIdx.x;
    int i = blockIdx.x * SB + t;
    int v = (i < N) ? g_deg_in[i] : 0;
    s[t] = v;
    __syncthreads();
    for (int d = 1; d < SB; d <<= 1) {
        int u = (t >= d) ? s[t - d] : 0;
        __syncthreads();
        s[t] += u;
        __syncthreads();
    }
    if (i < N) {
        int off = g_bpre[blockIdx.x] + s[t] - v;   // global exclusive prefix
        g_off[i] = off;
        g_cursor[i] = off;
    }
}

// ---------------------------------------------------------------- per-node prep: xsn = x[:,15:25]*norm_s
__global__ void k_prep(const float* __restrict__ x, int N) {
    int i = blockIdx.x * blockDim.x + threadIdx.x;
    if (i >= N) return;
    int dout = g_deg_out[i];
    float ns = rsqrtf(dout > 0 ? (float)dout : 1.f);
    const float* base = x + (size_t)i * 40;
    float4 L0 = *reinterpret_cast<const float4*>(base + 12);  // cols 12-15
    float4 L1 = *reinterpret_cast<const float4*>(base + 16);  // cols 16-19
    float4 L2 = *reinterpret_cast<const float4*>(base + 20);  // cols 20-23
    float4 L3 = *reinterpret_cast<const float4*>(base + 24);  // cols 24-27
    float4* o = reinterpret_cast<float4*>(g_xsn + i * FP);
    o[0] = make_float4(L0.w * ns, L1.x * ns, L1.y * ns, L1.z * ns);   // c15-18
    o[1] = make_float4(L1.w * ns, L2.x * ns, L2.y * ns, L2.z * ns);   // c19-22
    o[2] = make_float4(L2.w * ns, L3.x * ns, 0.f, 0.f);               // c23-24 + pad
}

// ---------------------------------------------------------------- bin edges by dst
__global__ void k_bin(const int* __restrict__ src, const int* __restrict__ dst, int E) {
    int t = blockIdx.x * blockDim.x + threadIdx.x;
    int nq = E >> 2;
    if (t < nq) {
        int4 s = reinterpret_cast<const int4*>(src)[t];
        int4 d = reinterpret_cast<const int4*>(dst)[t];
        int p0 = atomicAdd(&g_cursor[d.x], 1);
        int p1 = atomicAdd(&g_cursor[d.y], 1);
        int p2 = atomicAdd(&g_cursor[d.z], 1);
        int p3 = atomicAdd(&g_cursor[d.w], 1);
        g_esrc[p0] = s.x;
        g_esrc[p1] = s.y;
        g_esrc[p2] = s.z;
        g_esrc[p3] = s.w;
    }
    if (t == 0) {
        for (int e = (nq << 2); e < E; e++) {
            int p = atomicAdd(&g_cursor[dst[e]], 1);
            g_esrc[p] = src[e];
        }
    }
}

// ---------------------------------------------------------------- fold MLP
__global__ void k_weff(const float* __restrict__ W1, const float* __restrict__ b1,
                       const float* __restrict__ W2, const float* __restrict__ b2) {
    int t = threadIdx.x;
    if (t < 640) {
        int i = t >> 6, j = t & 63;
        float s = 0.f;
#pragma unroll 8
        for (int k = 0; k < 128; k++) s += W1[i * 128 + k] * W2[k * 64 + j];
        g_Weff[t] = s;
    } else if (t < 704) {
        int j = t - 640;
        float s = b2[j];
#pragma unroll 8
        for (int k = 0; k < 128; k++) s += b1[k] * W2[k * 64 + j];
        g_beff[j] = s;
    }
}

// ---------------------------------------------------------------- warp-per-node gather + fused output matvec
__global__ void __launch_bounds__(512) k_gather_out(float* __restrict__ out, int N) {
    __shared__ float sW[640];
    __shared__ float sb[64];
    int t = threadIdx.x;
    for (int k = t; k < 640; k += 512) sW[k] = g_Weff[k];
    if (t < 64) sb[t] = g_beff[t];
    __syncthreads();

    int warp = t >> 5, lane = t & 31;
    int node = blockIdx.x * 16 + warp;
    if (node >= N) return;

    int beg = g_off[node];
    int end = g_cursor[node];          // = beg + deg_in[node] after binning
    int cnt = end - beg;

    float4 a0 = {0.f, 0.f, 0.f, 0.f};
    float4 a1 = {0.f, 0.f, 0.f, 0.f};
    float2 a2 = {0.f, 0.f};
    for (int i = beg + lane; i < end; i += 32) {
        int s = __ldg(&g_esrc[i]);
        const float* r = g_xsn + s * FP;
        float4 v0 = *reinterpret_cast<const float4*>(r);
        float4 v1 = *reinterpret_cast<const float4*>(r + 4);
        float2 v2 = *reinterpret_cast<const float2*>(r + 8);
        a0.x += v0.x; a0.y += v0.y; a0.z += v0.z; a0.w += v0.w;
        a1.x += v1.x; a1.y += v1.y; a1.z += v1.z; a1.w += v1.w;
        a2.x += v2.x; a2.y += v2.y;
    }

    // butterfly reduce — all lanes end with the full sums
#pragma unroll
    for (int off = 16; off >= 1; off >>= 1) {
        a0.x += __shfl_xor_sync(0xffffffffu, a0.x, off);
        a0.y += __shfl_xor_sync(0xffffffffu, a0.y, off);
        a0.z += __shfl_xor_sync(0xffffffffu, a0.z, off);
        a0.w += __shfl_xor_sync(0xffffffffu, a0.w, off);
        a1.x += __shfl_xor_sync(0xffffffffu, a1.x, off);
        a1.y += __shfl_xor_sync(0xffffffffu, a1.y, off);
        a1.z += __shfl_xor_sync(0xffffffffu, a1.z, off);
        a1.w += __shfl_xor_sync(0xffffffffu, a1.w, off);
        a2.x += __shfl_xor_sync(0xffffffffu, a2.x, off);
        a2.y += __shfl_xor_sync(0xffffffffu, a2.y, off);
    }

    float nd = rsqrtf(cnt > 0 ? (float)cnt : 1.f);
    float a[10] = {a0.x * nd, a0.y * nd, a0.z * nd, a0.w * nd,
                   a1.x * nd, a1.y * nd, a1.z * nd, a1.w * nd,
                   a2.x * nd, a2.y * nd};

    float acc0 = sb[lane];
    float acc1 = sb[lane + 32];
#pragma unroll
    for (int k = 0; k < 10; k++) {
        acc0 += a[k] * sW[k * 64 + lane];
        acc1 += a[k] * sW[k * 64 + lane + 32];
    }
    size_t ob = (size_t)node * 64;
    out[ob + lane]      = acc0;
    out[ob + lane + 32] = acc1;
}

// ---------------------------------------------------------------- launch
extern "C" void kernel_launch(void* const* d_in, const int* in_sizes, int n_in,
                              void* d_out, int out_size) {
    const float* x   = (const float*)d_in[0];
    const int*   src = (const int*)d_in[1];
    const int*   dst = (const int*)d_in[2];
    const float* W1  = (const float*)d_in[3];
    const float* b1  = (const float*)d_in[4];
    const float* W2  = (const float*)d_in[5];
    const float* b2  = (const float*)d_in[6];
    float* out = (float*)d_out;

    int N = in_sizes[0] / 40;
    int E = in_sizes[1];
    int nq = E >> 2;
    int eb = nq > 0 ? (nq + 255) / 256 : 1;
    int NB = (N + SB - 1) / SB;     // <= 391 for N=100k

    k_zero<<<128, 256>>>(N);
    k_weff<<<1, 704>>>(W1, b1, W2, b2);
    k_degree<<<eb, 256>>>(src, dst, E);
    k_scan1<<<NB, SB>>>(N);
    k_scan2<<<1, 512>>>(NB);
    k_scan3<<<NB, SB>>>(N);
    k_prep<<<(N + 255) / 256, 256>>>(x, N);
    k_bin<<<eb, 256>>>(src, dst, E);
    k_gather_out<<<(N + 15) / 16, 512>>>(out, N);
}

// round 4
// speedup vs baseline: 2.2468x; 1.1166x over previous
#include <cuda_runtime.h>

// GCN_75050258530542 — round 4: single-pass vector-RED scatter, in-band deg_in
// count (slot 10 of each agg row), deg_out-only degree pass, 64B padded rows.
// out[n,:] = rsqrt(deg_in[n]) * (sum_{e:dst=n} x[src,15:25]*rsqrt(deg_out[src])) @ (W1@W2)
//            + (b1@W2 + b2)

constexpr int NMAX = 100000;
constexpr int FP   = 16;   // 64B rows: any 48B prefix lives in one 128B line

__device__ int   g_deg_out[NMAX];
__device__ __align__(16) float g_xsn[NMAX * FP];   // x[:,15:25] * norm_s (slots 0-9)
__device__ __align__(16) float g_agg[NMAX * FP];   // slots 0-9 sums, slot 10 = deg_in
__device__ float g_Weff[640];                      // W1@W2 (10 x 64)
__device__ float g_beff[64];                       // b1@W2 + b2

// ---------------------------------------------------------------- zero agg + deg_out
__global__ void k_zero(int N) {
    int i = blockIdx.x * blockDim.x + threadIdx.x;
    int stride = gridDim.x * blockDim.x;
    float4 z = {0.f, 0.f, 0.f, 0.f};
    float4* a = reinterpret_cast<float4*>(g_agg);
    int nq = N * 4;                       // N*FP/4 float4s
    for (int k = i; k < nq; k += stride) a[k] = z;
    for (int k = i; k < N; k += stride) g_deg_out[k] = 0;
}

// ---------------------------------------------------------------- out-degrees only
__global__ void k_degree(const int* __restrict__ src, int E) {
    int t = blockIdx.x * blockDim.x + threadIdx.x;
    int n8 = E >> 3;
    if (t < n8) {
        int4 s0 = reinterpret_cast<const int4*>(src)[2 * t];
        int4 s1 = reinterpret_cast<const int4*>(src)[2 * t + 1];
        atomicAdd(&g_deg_out[s0.x], 1);
        atomicAdd(&g_deg_out[s0.y], 1);
        atomicAdd(&g_deg_out[s0.z], 1);
        atomicAdd(&g_deg_out[s0.w], 1);
        atomicAdd(&g_deg_out[s1.x], 1);
        atomicAdd(&g_deg_out[s1.y], 1);
        atomicAdd(&g_deg_out[s1.z], 1);
        atomicAdd(&g_deg_out[s1.w], 1);
    }
    if (t == 0) {
        for (int e = (n8 << 3); e < E; e++) atomicAdd(&g_deg_out[src[e]], 1);
    }
}

// ---------------------------------------------------------------- prep: xsn = x[:,15:25]*norm_s
__global__ void k_prep(const float* __restrict__ x, int N) {
    int i = blockIdx.x * blockDim.x + threadIdx.x;
    if (i >= N) return;
    int dout = g_deg_out[i];
    float ns = rsqrtf(dout > 0 ? (float)dout : 1.f);
    const float* base = x + (size_t)i * 40;
    float4 L0 = *reinterpret_cast<const float4*>(base + 12);  // cols 12-15
    float4 L1 = *reinterpret_cast<const float4*>(base + 16);  // cols 16-19
    float4 L2 = *reinterpret_cast<const float4*>(base + 20);  // cols 20-23
    float4 L3 = *reinterpret_cast<const float4*>(base + 24);  // cols 24-27
    float* o = g_xsn + i * FP;
    *reinterpret_cast<float4*>(o)     = make_float4(L0.w * ns, L1.x * ns, L1.y * ns, L1.z * ns); // c15-18
    *reinterpret_cast<float4*>(o + 4) = make_float4(L1.w * ns, L2.x * ns, L2.y * ns, L2.z * ns); // c19-22
    *reinterpret_cast<float2*>(o + 8) = make_float2(L2.w * ns, L3.x * ns);                       // c23-24
}

// ---------------------------------------------------------------- vector REDs
__device__ __forceinline__ void red4(float* p, float a, float b, float c, float d) {
    asm volatile("red.global.add.v4.f32 [%0], {%1,%2,%3,%4};"
                 :: "l"(p), "f"(a), "f"(b), "f"(c), "f"(d) : "memory");
}

// ---------------------------------------------------------------- scatter (8 edges/thread), count in-band
__global__ void k_scatter(const int* __restrict__ src, const int* __restrict__ dst, int E) {
    int t = blockIdx.x * blockDim.x + threadIdx.x;
    int n8 = E >> 3;
    if (t < n8) {
        int4 s0 = reinterpret_cast<const int4*>(src)[2 * t];
        int4 s1 = reinterpret_cast<const int4*>(src)[2 * t + 1];
        int4 d0 = reinterpret_cast<const int4*>(dst)[2 * t];
        int4 d1 = reinterpret_cast<const int4*>(dst)[2 * t + 1];
        int ss[8] = {s0.x, s0.y, s0.z, s0.w, s1.x, s1.y, s1.z, s1.w};
        int dd[8] = {d0.x, d0.y, d0.z, d0.w, d1.x, d1.y, d1.z, d1.w};
        float4 A[8], B[8];
        float2 C[8];
#pragma unroll
        for (int j = 0; j < 8; j++) {
            const float* r = g_xsn + ss[j] * FP;
            A[j] = *reinterpret_cast<const float4*>(r);
            B[j] = *reinterpret_cast<const float4*>(r + 4);
            C[j] = *reinterpret_cast<const float2*>(r + 8);
        }
#pragma unroll
        for (int j = 0; j < 8; j++) {
            float* a = g_agg + dd[j] * FP;
            red4(a,     A[j].x, A[j].y, A[j].z, A[j].w);
            red4(a + 4, B[j].x, B[j].y, B[j].z, B[j].w);
            red4(a + 8, C[j].x, C[j].y, 1.0f, 0.0f);      // slot 10 += 1 (deg_in), free
        }
    }
    if (t == 0) {
        for (int e = (n8 << 3); e < E; e++) {
            const float* r = g_xsn + src[e] * FP;
            float* a = g_agg + dst[e] * FP;
            red4(a,     r[0], r[1], r[2], r[3]);
            red4(a + 4, r[4], r[5], r[6], r[7]);
            red4(a + 8, r[8], r[9], 1.0f, 0.0f);
        }
    }
}

// ---------------------------------------------------------------- fold MLP
__global__ void k_weff(const float* __restrict__ W1, const float* __restrict__ b1,
                       const float* __restrict__ W2, const float* __restrict__ b2) {
    int t = threadIdx.x;
    if (t < 640) {
        int i = t >> 6, j = t & 63;
        float s = 0.f;
#pragma unroll 8
        for (int k = 0; k < 128; k++) s += W1[i * 128 + k] * W2[k * 64 + j];
        g_Weff[t] = s;
    } else if (t < 704) {
        int j = t - 640;
        float s = b2[j];
#pragma unroll 8
        for (int k = 0; k < 128; k++) s += b1[k] * W2[k * 64 + j];
        g_beff[j] = s;
    }
}

// ---------------------------------------------------------------- output matvec
__global__ void k_out(float* __restrict__ out, int N) {
    __shared__ float sW[640];
    __shared__ float sb[64];
    int t = threadIdx.x;
    for (int k = t; k < 640; k += 256) sW[k] = g_Weff[k];
    if (t < 64) sb[t] = g_beff[t];
    __syncthreads();
    int node = blockIdx.x * 4 + (t >> 6);
    if (node >= N) return;
    int j = t & 63;
    const float* ar = g_agg + node * FP;
    float4 a0 = *reinterpret_cast<const float4*>(ar);
    float4 a1 = *reinterpret_cast<const float4*>(ar + 4);
    float4 a2 = *reinterpret_cast<const float4*>(ar + 8);   // a2.z = deg_in count
    float cnt = a2.z;
    float nd = rsqrtf(cnt > 0.f ? cnt : 1.f);
    float a[10] = {a0.x, a0.y, a0.z, a0.w, a1.x, a1.y, a1.z, a1.w, a2.x, a2.y};
    float acc = sb[j];
#pragma unroll
    for (int k = 0; k < 10; k++) acc += (a[k] * nd) * sW[k * 64 + j];
    out[(size_t)node * 64 + j] = acc;
}

// ---------------------------------------------------------------- launch
extern "C" void kernel_launch(void* const* d_in, const int* in_sizes, int n_in,
                              void* d_out, int out_size) {
    const float* x   = (const float*)d_in[0];
    const int*   src = (const int*)d_in[1];
    const int*   dst = (const int*)d_in[2];
    const float* W1  = (const float*)d_in[3];
    const float* b1  = (const float*)d_in[4];
    const float* W2  = (const float*)d_in[5];
    const float* b2  = (const float*)d_in[6];
    float* out = (float*)d_out;

    int N = in_sizes[0] / 40;
    int E = in_sizes[1];
    int n8 = E >> 3;
    int eb = n8 > 0 ? (n8 + 255) / 256 : 1;

    k_zero<<<1024, 256>>>(N);
    k_weff<<<1, 704>>>(W1, b1, W2, b2);
    k_degree<<<eb, 256>>>(src, E);
    k_prep<<<(N + 255) / 256, 256>>>(x, N);
    k_scatter<<<eb, 256>>>(src, dst, E);
    k_out<<<(N + 3) / 4, 256>>>(out, N);
}

// round 5
// speedup vs baseline: 2.6116x; 1.1624x over previous
#include <cuda_runtime.h>

// GCN_75050258530542 — round 5: cooperative 4-lane scatter (1 gather wavefront
// + 1 RED wavefront per edge), in-band deg_in count, memset-based zeroing.
// out[n,:] = rsqrt(deg_in[n]) * (sum_{e:dst=n} x[src,15:25]*rsqrt(deg_out[src])) @ (W1@W2)
//            + (b1@W2 + b2)

constexpr int NMAX = 100000;
constexpr int FP   = 16;   // 64B rows, 128B-aligned array: 4-lane group = 1 line

__device__ int g_deg_out[NMAX];
__device__ __align__(128) float g_xsn[NMAX * FP];   // slots 0-9 = x[:,15:25]*norm_s; 10-15 = 0
__device__ __align__(128) float g_agg[NMAX * FP];   // slots 0-9 sums, slot 10 = deg_in
__device__ float g_Weff[640];                       // W1@W2 (10 x 64)
__device__ float g_beff[64];                        // b1@W2 + b2

// ---------------------------------------------------------------- degrees + weff (last block)
__global__ void k_deg_weff(const int* __restrict__ src, int E,
                           const float* __restrict__ W1, const float* __restrict__ b1,
                           const float* __restrict__ W2, const float* __restrict__ b2) {
    int nb = gridDim.x - 1;
    if ((int)blockIdx.x == nb) {
        // fold MLP: Weff = W1@W2, beff = b1@W2+b2
        for (int idx = threadIdx.x; idx < 704; idx += blockDim.x) {
            if (idx < 640) {
                int i = idx >> 6, j = idx & 63;
                float s = 0.f;
#pragma unroll 8
                for (int k = 0; k < 128; k++) s += W1[i * 128 + k] * W2[k * 64 + j];
                g_Weff[idx] = s;
            } else {
                int j = idx - 640;
                float s = b2[j];
#pragma unroll 8
                for (int k = 0; k < 128; k++) s += b1[k] * W2[k * 64 + j];
                g_beff[j] = s;
            }
        }
        return;
    }
    int n8 = E >> 3;
    int stride = nb * blockDim.x;
    for (int t = blockIdx.x * blockDim.x + threadIdx.x; t < n8; t += stride) {
        int4 s0 = reinterpret_cast<const int4*>(src)[2 * t];
        int4 s1 = reinterpret_cast<const int4*>(src)[2 * t + 1];
        atomicAdd(&g_deg_out[s0.x], 1);
        atomicAdd(&g_deg_out[s0.y], 1);
        atomicAdd(&g_deg_out[s0.z], 1);
        atomicAdd(&g_deg_out[s0.w], 1);
        atomicAdd(&g_deg_out[s1.x], 1);
        atomicAdd(&g_deg_out[s1.y], 1);
        atomicAdd(&g_deg_out[s1.z], 1);
        atomicAdd(&g_deg_out[s1.w], 1);
    }
    if (blockIdx.x == 0 && threadIdx.x == 0) {
        for (int e = (n8 << 3); e < E; e++) atomicAdd(&g_deg_out[src[e]], 1);
    }
}

// ---------------------------------------------------------------- prep: xsn = x[:,15:25]*norm_s
__global__ void k_prep(const float* __restrict__ x, int N) {
    int i = blockIdx.x * blockDim.x + threadIdx.x;
    if (i >= N) return;
    int dout = g_deg_out[i];
    float ns = rsqrtf(dout > 0 ? (float)dout : 1.f);
    const float* base = x + (size_t)i * 40;
    float4 L0 = *reinterpret_cast<const float4*>(base + 12);  // cols 12-15
    float4 L1 = *reinterpret_cast<const float4*>(base + 16);  // cols 16-19
    float4 L2 = *reinterpret_cast<const float4*>(base + 20);  // cols 20-23
    float4 L3 = *reinterpret_cast<const float4*>(base + 24);  // cols 24-27
    float* o = g_xsn + i * FP;
    *reinterpret_cast<float4*>(o)     = make_float4(L0.w * ns, L1.x * ns, L1.y * ns, L1.z * ns); // c15-18
    *reinterpret_cast<float4*>(o + 4) = make_float4(L1.w * ns, L2.x * ns, L2.y * ns, L2.z * ns); // c19-22
    *reinterpret_cast<float4*>(o + 8) = make_float4(L2.w * ns, L3.x * ns, 0.f, 0.f);             // c23-24, pad
}

// ---------------------------------------------------------------- vector RED
__device__ __forceinline__ void red4(float* p, float a, float b, float c, float d) {
    asm volatile("red.global.add.v4.f32 [%0], {%1,%2,%3,%4};"
                 :: "l"(p), "f"(a), "f"(b), "f"(c), "f"(d) : "memory");
}

// ---------------------------------------------------------------- scatter: 4 lanes per edge, 8 edges per group
__global__ void __launch_bounds__(256) k_scatter(const int* __restrict__ src,
                                                 const int* __restrict__ dst, int E) {
    int tid = blockIdx.x * blockDim.x + threadIdx.x;
    int g = tid >> 2;          // edge group
    int q = tid & 3;           // quarter within row
    long base = (long)g * 8;
    if (base >= E) return;
    int cnt = (int)(((long)E - base < 8) ? (E - base) : 8);

    int dd[8];
    float4 v[8];
#pragma unroll 8
    for (int j = 0; j < 8; j++) {
        if (j < cnt) {
            int s = __ldg(src + base + j);
            dd[j] = __ldg(dst + base + j);
            if (q < 3) v[j] = *reinterpret_cast<const float4*>(g_xsn + (size_t)s * FP + q * 4);
        }
    }
    if (q < 3) {
#pragma unroll 8
        for (int j = 0; j < 8; j++) {
            if (j < cnt) {
                float4 p = v[j];
                if (q == 2) { p.z = 1.0f; p.w = 0.0f; }   // slot 10 += 1 (deg_in)
                red4(g_agg + (size_t)dd[j] * FP + q * 4, p.x, p.y, p.z, p.w);
            }
        }
    }
}

// ---------------------------------------------------------------- output matvec
__global__ void k_out(float* __restrict__ out, int N) {
    __shared__ float sW[640];
    __shared__ float sb[64];
    int t = threadIdx.x;
    for (int k = t; k < 640; k += 256) sW[k] = g_Weff[k];
    if (t < 64) sb[t] = g_beff[t];
    __syncthreads();
    int node = blockIdx.x * 4 + (t >> 6);
    if (node >= N) return;
    int j = t & 63;
    const float* ar = g_agg + (size_t)node * FP;
    float4 a0 = *reinterpret_cast<const float4*>(ar);
    float4 a1 = *reinterpret_cast<const float4*>(ar + 4);
    float4 a2 = *reinterpret_cast<const float4*>(ar + 8);   // a2.z = deg_in count
    float cnt = a2.z;
    float nd = rsqrtf(cnt > 0.f ? cnt : 1.f);
    float a[10] = {a0.x, a0.y, a0.z, a0.w, a1.x, a1.y, a1.z, a1.w, a2.x, a2.y};
    float acc = sb[j];
#pragma unroll
    for (int k = 0; k < 10; k++) acc += (a[k] * nd) * sW[k * 64 + j];
    out[(size_t)node * 64 + j] = acc;
}

// ---------------------------------------------------------------- launch
extern "C" void kernel_launch(void* const* d_in, const int* in_sizes, int n_in,
                              void* d_out, int out_size) {
    const float* x   = (const float*)d_in[0];
    const int*   src = (const int*)d_in[1];
    const int*   dst = (const int*)d_in[2];
    const float* W1  = (const float*)d_in[3];
    const float* b1  = (const float*)d_in[4];
    const float* W2  = (const float*)d_in[5];
    const float* b2  = (const float*)d_in[6];
    float* out = (float*)d_out;

    int N = in_sizes[0] / 40;
    int E = in_sizes[1];

    void* p_agg = nullptr;
    void* p_deg = nullptr;
    cudaGetSymbolAddress(&p_agg, g_agg);
    cudaGetSymbolAddress(&p_deg, g_deg_out);
    cudaMemsetAsync(p_agg, 0, (size_t)N * FP * sizeof(float));
    cudaMemsetAsync(p_deg, 0, (size_t)N * sizeof(int));

    int n8 = E >> 3;
    int db = (n8 > 0 ? (n8 + 255) / 256 : 1) + 1;          // +1 block for weff
    k_deg_weff<<<db, 256>>>(src, E, W1, b1, W2, b2);
    k_prep<<<(N + 255) / 256, 256>>>(x, N);

    long groups = ((long)E + 7) / 8;                        // 4 lanes per group
    long sthreads = groups * 4;
    int sblocks = (int)((sthreads + 255) / 256);
    k_scatter<<<sblocks, 256>>>(src, dst, E);

    k_out<<<(N + 3) / 4, 256>>>(out, N);
}

// round 6
// speedup vs baseline: 2.9240x; 1.1196x over previous
#include <cuda_runtime.h>

// GCN_75050258530542 — round 6: persistent k_out (smem Weff loaded once per
// block), shuffle-dedup edge-index loads in scatter. Pipeline otherwise as R5.
// out[n,:] = rsqrt(deg_in[n]) * (sum_{e:dst=n} x[src,15:25]*rsqrt(deg_out[src])) @ (W1@W2)
//            + (b1@W2 + b2)

constexpr int NMAX = 100000;
constexpr int FP   = 16;   // 64B rows, 128B-aligned: 4-lane group hits 1 line

__device__ int g_deg_out[NMAX];
__device__ __align__(128) float g_xsn[NMAX * FP];   // slots 0-9 = x[:,15:25]*norm_s; 10-15 = 0
__device__ __align__(128) float g_agg[NMAX * FP];   // slots 0-9 sums, slot 10 = deg_in
__device__ float g_Weff[640];                       // W1@W2 (10 x 64)
__device__ float g_beff[64];                        // b1@W2 + b2

// ---------------------------------------------------------------- degrees + weff (last block)
__global__ void k_deg_weff(const int* __restrict__ src, int E,
                           const float* __restrict__ W1, const float* __restrict__ b1,
                           const float* __restrict__ W2, const float* __restrict__ b2) {
    int nb = gridDim.x - 1;
    if ((int)blockIdx.x == nb) {
        for (int idx = threadIdx.x; idx < 704; idx += blockDim.x) {
            if (idx < 640) {
                int i = idx >> 6, j = idx & 63;
                float s = 0.f;
#pragma unroll 8
                for (int k = 0; k < 128; k++) s += W1[i * 128 + k] * W2[k * 64 + j];
                g_Weff[idx] = s;
            } else {
                int j = idx - 640;
                float s = b2[j];
#pragma unroll 8
                for (int k = 0; k < 128; k++) s += b1[k] * W2[k * 64 + j];
                g_beff[j] = s;
            }
        }
        return;
    }
    int n8 = E >> 3;
    int stride = nb * blockDim.x;
    for (int t = blockIdx.x * blockDim.x + threadIdx.x; t < n8; t += stride) {
        int4 s0 = reinterpret_cast<const int4*>(src)[2 * t];
        int4 s1 = reinterpret_cast<const int4*>(src)[2 * t + 1];
        atomicAdd(&g_deg_out[s0.x], 1);
        atomicAdd(&g_deg_out[s0.y], 1);
        atomicAdd(&g_deg_out[s0.z], 1);
        atomicAdd(&g_deg_out[s0.w], 1);
        atomicAdd(&g_deg_out[s1.x], 1);
        atomicAdd(&g_deg_out[s1.y], 1);
        atomicAdd(&g_deg_out[s1.z], 1);
        atomicAdd(&g_deg_out[s1.w], 1);
    }
    if (blockIdx.x == 0 && threadIdx.x == 0) {
        for (int e = (n8 << 3); e < E; e++) atomicAdd(&g_deg_out[src[e]], 1);
    }
}

// ---------------------------------------------------------------- prep: xsn = x[:,15:25]*norm_s
__global__ void k_prep(const float* __restrict__ x, int N) {
    int i = blockIdx.x * blockDim.x + threadIdx.x;
    if (i >= N) return;
    int dout = g_deg_out[i];
    float ns = rsqrtf(dout > 0 ? (float)dout : 1.f);
    const float* base = x + (size_t)i * 40;
    float4 L0 = *reinterpret_cast<const float4*>(base + 12);  // cols 12-15
    float4 L1 = *reinterpret_cast<const float4*>(base + 16);  // cols 16-19
    float4 L2 = *reinterpret_cast<const float4*>(base + 20);  // cols 20-23
    float4 L3 = *reinterpret_cast<const float4*>(base + 24);  // cols 24-27
    float* o = g_xsn + i * FP;
    *reinterpret_cast<float4*>(o)     = make_float4(L0.w * ns, L1.x * ns, L1.y * ns, L1.z * ns); // c15-18
    *reinterpret_cast<float4*>(o + 4) = make_float4(L1.w * ns, L2.x * ns, L2.y * ns, L2.z * ns); // c19-22
    *reinterpret_cast<float4*>(o + 8) = make_float4(L2.w * ns, L3.x * ns, 0.f, 0.f);             // c23-24, pad
}

// ---------------------------------------------------------------- vector RED
__device__ __forceinline__ void red4(float* p, float a, float b, float c, float d) {
    asm volatile("red.global.add.v4.f32 [%0], {%1,%2,%3,%4};"
                 :: "l"(p), "f"(a), "f"(b), "f"(c), "f"(d) : "memory");
}

// ---------------------------------------------------------------- scatter: 4 lanes/edge, 8 edges/group
__global__ void __launch_bounds__(256) k_scatter(const int* __restrict__ src,
                                                 const int* __restrict__ dst, int E) {
    int tid = blockIdx.x * blockDim.x + threadIdx.x;
    int g = tid >> 2;          // edge group (8 edges)
    int q = tid & 3;           // quarter within feature row
    long base = (long)g * 8;
    if (base >= E) return;

    unsigned am = 0xffffffffu;
    int full = (base + 8 <= (long)E);
    int cnt = full ? 8 : (int)(E - base);

    int dd[8];
    float4 v[8];
    if (full) {
        // lane q loads edges {2q, 2q+1}; shuffle-broadcast to the group
        int s2a = __ldg(src + base + 2 * q);
        int s2b = __ldg(src + base + 2 * q + 1);
        int d2a = __ldg(dst + base + 2 * q);
        int d2b = __ldg(dst + base + 2 * q + 1);
        int lq = (tid & 31) & ~3;   // group leader lane offset in warp
#pragma unroll
        for (int j = 0; j < 8; j++) {
            int owner = lq + (j >> 1);
            int sj = __shfl_sync(am, (j & 1) ? s2b : s2a, owner);
            dd[j]  = __shfl_sync(am, (j & 1) ? d2b : d2a, owner);
            if (q < 3) v[j] = *reinterpret_cast<const float4*>(g_xsn + (size_t)sj * FP + q * 4);
        }
#pragma unroll
        for (int j = 0; j < 8; j++) {
            if (q < 3) {
                float4 p = v[j];
                if (q == 2) { p.z = 1.0f; p.w = 0.0f; }   // slot 10 += 1 (deg_in)
                red4(g_agg + (size_t)dd[j] * FP + q * 4, p.x, p.y, p.z, p.w);
            }
        }
    } else {
        for (int j = 0; j < cnt; j++) {
            int sj = __ldg(src + base + j);
            int dj = __ldg(dst + base + j);
            if (q < 3) {
                float4 p = *reinterpret_cast<const float4*>(g_xsn + (size_t)sj * FP + q * 4);
                if (q == 2) { p.z = 1.0f; p.w = 0.0f; }
                red4(g_agg + (size_t)dj * FP + q * 4, p.x, p.y, p.z, p.w);
            }
        }
    }
}

// ---------------------------------------------------------------- persistent output matvec
__global__ void __launch_bounds__(256) k_out(float* __restrict__ out, int N) {
    __shared__ float sW[640];
    __shared__ float sb[64];
    int t = threadIdx.x;
    for (int k = t; k < 640; k += 256) sW[k] = g_Weff[k];
    if (t < 64) sb[t] = g_beff[t];
    __syncthreads();

    int j = t & 63;
    int sub = t >> 6;                         // 0..3 nodes per block-iteration
    int step = gridDim.x * 4;
    for (int node = blockIdx.x * 4 + sub; node < N; node += step) {
        const float* ar = g_agg + (size_t)node * FP;
        float4 a0 = *reinterpret_cast<const float4*>(ar);
        float4 a1 = *reinterpret_cast<const float4*>(ar + 4);
        float4 a2 = *reinterpret_cast<const float4*>(ar + 8);   // a2.z = deg_in
        float cnt = a2.z;
        float nd = rsqrtf(cnt > 0.f ? cnt : 1.f);
        float a[10] = {a0.x, a0.y, a0.z, a0.w, a1.x, a1.y, a1.z, a1.w, a2.x, a2.y};
        float acc = sb[j];
#pragma unroll
        for (int k = 0; k < 10; k++) acc += (a[k] * nd) * sW[k * 64 + j];
        out[(size_t)node * 64 + j] = acc;
    }
}

// ---------------------------------------------------------------- launch
extern "C" void kernel_launch(void* const* d_in, const int* in_sizes, int n_in,
                              void* d_out, int out_size) {
    const float* x   = (const float*)d_in[0];
    const int*   src = (const int*)d_in[1];
    const int*   dst = (const int*)d_in[2];
    const float* W1  = (const float*)d_in[3];
    const float* b1  = (const float*)d_in[4];
    const float* W2  = (const float*)d_in[5];
    const float* b2  = (const float*)d_in[6];
    float* out = (float*)d_out;

    int N = in_sizes[0] / 40;
    int E = in_sizes[1];

    void* p_agg = nullptr;
    void* p_deg = nullptr;
    cudaGetSymbolAddress(&p_agg, g_agg);
    cudaGetSymbolAddress(&p_deg, g_deg_out);
    cudaMemsetAsync(p_agg, 0, (size_t)N * FP * sizeof(float));
    cudaMemsetAsync(p_deg, 0, (size_t)N * sizeof(int));

    int n8 = E >> 3;
    int db = (n8 > 0 ? (n8 + 255) / 256 : 1) + 1;          // +1 block for weff
    k_deg_weff<<<db, 256>>>(src, E, W1, b1, W2, b2);
    k_prep<<<(N + 255) / 256, 256>>>(x, N);

    long groups = ((long)E + 7) / 8;                        // 4 lanes per group
    long sthreads = groups * 4;
    int sblocks = (int)((sthreads + 255) / 256);
    k_scatter<<<sblocks, 256>>>(src, dst, E);

    k_out<<<592, 256>>>(out, N);                            // persistent, ~4 blocks/SM
}

// round 7
// speedup vs baseline: 2.9266x; 1.0009x over previous
#include <cuda_runtime.h>

// GCN_75050258530542 — round 7: k_out batches 4 nodes/iteration (MLP=12 to
// hide L2 latency, weights hoisted to registers). Scatter/degree as R6.
// out[n,:] = rsqrt(deg_in[n]) * (sum_{e:dst=n} x[src,15:25]*rsqrt(deg_out[src])) @ (W1@W2)
//            + (b1@W2 + b2)

constexpr int NMAX = 100000;
constexpr int FP   = 16;   // 64B rows, 128B-aligned: 4-lane group hits 1 line

__device__ int g_deg_out[NMAX];
__device__ __align__(128) float g_xsn[NMAX * FP];   // slots 0-9 = x[:,15:25]*norm_s; 10-15 = 0
__device__ __align__(128) float g_agg[NMAX * FP];   // slots 0-9 sums, slot 10 = deg_in
__device__ float g_Weff[640];                       // W1@W2 (10 x 64)
__device__ float g_beff[64];                        // b1@W2 + b2

// ---------------------------------------------------------------- degrees + weff (last block)
__global__ void k_deg_weff(const int* __restrict__ src, int E,
                           const float* __restrict__ W1, const float* __restrict__ b1,
                           const float* __restrict__ W2, const float* __restrict__ b2) {
    int nb = gridDim.x - 1;
    if ((int)blockIdx.x == nb) {
        for (int idx = threadIdx.x; idx < 704; idx += blockDim.x) {
            if (idx < 640) {
                int i = idx >> 6, j = idx & 63;
                float s = 0.f;
#pragma unroll 8
                for (int k = 0; k < 128; k++) s += W1[i * 128 + k] * W2[k * 64 + j];
                g_Weff[idx] = s;
            } else {
                int j = idx - 640;
                float s = b2[j];
#pragma unroll 8
                for (int k = 0; k < 128; k++) s += b1[k] * W2[k * 64 + j];
                g_beff[j] = s;
            }
        }
        return;
    }
    int n8 = E >> 3;
    int stride = nb * blockDim.x;
    for (int t = blockIdx.x * blockDim.x + threadIdx.x; t < n8; t += stride) {
        int4 s0 = reinterpret_cast<const int4*>(src)[2 * t];
        int4 s1 = reinterpret_cast<const int4*>(src)[2 * t + 1];
        atomicAdd(&g_deg_out[s0.x], 1);
        atomicAdd(&g_deg_out[s0.y], 1);
        atomicAdd(&g_deg_out[s0.z], 1);
        atomicAdd(&g_deg_out[s0.w], 1);
        atomicAdd(&g_deg_out[s1.x], 1);
        atomicAdd(&g_deg_out[s1.y], 1);
        atomicAdd(&g_deg_out[s1.z], 1);
        atomicAdd(&g_deg_out[s1.w], 1);
    }
    if (blockIdx.x == 0 && threadIdx.x == 0) {
        for (int e = (n8 << 3); e < E; e++) atomicAdd(&g_deg_out[src[e]], 1);
    }
}

// ---------------------------------------------------------------- prep: xsn = x[:,15:25]*norm_s
__global__ void k_prep(const float* __restrict__ x, int N) {
    int i = blockIdx.x * blockDim.x + threadIdx.x;
    if (i >= N) return;
    int dout = g_deg_out[i];
    float ns = rsqrtf(dout > 0 ? (float)dout : 1.f);
    const float* base = x + (size_t)i * 40;
    float4 L0 = *reinterpret_cast<const float4*>(base + 12);  // cols 12-15
    float4 L1 = *reinterpret_cast<const float4*>(base + 16);  // cols 16-19
    float4 L2 = *reinterpret_cast<const float4*>(base + 20);  // cols 20-23
    float4 L3 = *reinterpret_cast<const float4*>(base + 24);  // cols 24-27
    float* o = g_xsn + i * FP;
    *reinterpret_cast<float4*>(o)     = make_float4(L0.w * ns, L1.x * ns, L1.y * ns, L1.z * ns); // c15-18
    *reinterpret_cast<float4*>(o + 4) = make_float4(L1.w * ns, L2.x * ns, L2.y * ns, L2.z * ns); // c19-22
    *reinterpret_cast<float4*>(o + 8) = make_float4(L2.w * ns, L3.x * ns, 0.f, 0.f);             // c23-24, pad
}

// ---------------------------------------------------------------- vector RED
__device__ __forceinline__ void red4(float* p, float a, float b, float c, float d) {
    asm volatile("red.global.add.v4.f32 [%0], {%1,%2,%3,%4};"
                 :: "l"(p), "f"(a), "f"(b), "f"(c), "f"(d) : "memory");
}

// ---------------------------------------------------------------- scatter: 4 lanes/edge, 8 edges/group
__global__ void __launch_bounds__(256) k_scatter(const int* __restrict__ src,
                                                 const int* __restrict__ dst, int E) {
    int tid = blockIdx.x * blockDim.x + threadIdx.x;
    int g = tid >> 2;          // edge group (8 edges)
    int q = tid & 3;           // quarter within feature row
    long base = (long)g * 8;
    if (base >= E) return;

    unsigned am = 0xffffffffu;
    int full = (base + 8 <= (long)E);

    int dd[8];
    float4 v[8];
    if (full) {
        int s2a = __ldg(src + base + 2 * q);
        int s2b = __ldg(src + base + 2 * q + 1);
        int d2a = __ldg(dst + base + 2 * q);
        int d2b = __ldg(dst + base + 2 * q + 1);
        int lq = (tid & 31) & ~3;
#pragma unroll
        for (int j = 0; j < 8; j++) {
            int owner = lq + (j >> 1);
            int sj = __shfl_sync(am, (j & 1) ? s2b : s2a, owner);
            dd[j]  = __shfl_sync(am, (j & 1) ? d2b : d2a, owner);
            if (q < 3) v[j] = *reinterpret_cast<const float4*>(g_xsn + (size_t)sj * FP + q * 4);
        }
#pragma unroll
        for (int j = 0; j < 8; j++) {
            if (q < 3) {
                float4 p = v[j];
                if (q == 2) { p.z = 1.0f; p.w = 0.0f; }   // slot 10 += 1 (deg_in)
                red4(g_agg + (size_t)dd[j] * FP + q * 4, p.x, p.y, p.z, p.w);
            }
        }
    } else {
        int cnt = (int)(E - base);
        for (int j = 0; j < cnt; j++) {
            int sj = __ldg(src + base + j);
            int dj = __ldg(dst + base + j);
            if (q < 3) {
                float4 p = *reinterpret_cast<const float4*>(g_xsn + (size_t)sj * FP + q * 4);
                if (q == 2) { p.z = 1.0f; p.w = 0.0f; }
                red4(g_agg + (size_t)dj * FP + q * 4, p.x, p.y, p.z, p.w);
            }
        }
    }
}

// ---------------------------------------------------------------- persistent output matvec, 4 nodes/iter
__global__ void __launch_bounds__(256) k_out(float* __restrict__ out, int N) {
    __shared__ float sW[640];
    __shared__ float sb[64];
    int t = threadIdx.x;
    for (int k = t; k < 640; k += 256) sW[k] = g_Weff[k];
    if (t < 64) sb[t] = g_beff[t];
    __syncthreads();

    int j = t & 63;
    int sub = t >> 6;                         // 0..3: warp-pair slot in block
    // hoist weights + bias into registers (loop-invariant)
    float w[10];
#pragma unroll
    for (int k = 0; k < 10; k++) w[k] = sW[k * 64 + j];
    float bj = sb[j];

    int step = gridDim.x * 16;                // 16 nodes per block-iteration
    for (int nb = blockIdx.x * 16 + sub * 4; nb < N; nb += step) {
        // front-batched loads: up to 12 independent LDG.128
        float4 a0[4], a1[4], a2[4];
        int nv = (N - nb < 4) ? (N - nb) : 4;
#pragma unroll
        for (int i = 0; i < 4; i++) {
            if (i < nv) {
                const float* ar = g_agg + (size_t)(nb + i) * FP;
                a0[i] = *reinterpret_cast<const float4*>(ar);
                a1[i] = *reinterpret_cast<const float4*>(ar + 4);
                a2[i] = *reinterpret_cast<const float4*>(ar + 8);   // .z = deg_in
            }
        }
#pragma unroll
        for (int i = 0; i < 4; i++) {
            if (i < nv) {
                float cnt = a2[i].z;
                float nd = rsqrtf(cnt > 0.f ? cnt : 1.f);
                float s = a0[i].x * w[0] + a0[i].y * w[1] + a0[i].z * w[2] + a0[i].w * w[3]
                        + a1[i].x * w[4] + a1[i].y * w[5] + a1[i].z * w[6] + a1[i].w * w[7]
                        + a2[i].x * w[8] + a2[i].y * w[9];
                out[(size_t)(nb + i) * 64 + j] = bj + nd * s;
            }
        }
    }
}

// ---------------------------------------------------------------- launch
extern "C" void kernel_launch(void* const* d_in, const int* in_sizes, int n_in,
                              void* d_out, int out_size) {
    const float* x   = (const float*)d_in[0];
    const int*   src = (const int*)d_in[1];
    const int*   dst = (const int*)d_in[2];
    const float* W1  = (const float*)d_in[3];
    const float* b1  = (const float*)d_in[4];
    const float* W2  = (const float*)d_in[5];
    const float* b2  = (const float*)d_in[6];
    float* out = (float*)d_out;

    int N = in_sizes[0] / 40;
    int E = in_sizes[1];

    void* p_agg = nullptr;
    void* p_deg = nullptr;
    cudaGetSymbolAddress(&p_agg, g_agg);
    cudaGetSymbolAddress(&p_deg, g_deg_out);
    cudaMemsetAsync(p_agg, 0, (size_t)N * FP * sizeof(float));
    cudaMemsetAsync(p_deg, 0, (size_t)N * sizeof(int));

    int n8 = E >> 3;
    int db = (n8 > 0 ? (n8 + 255) / 256 : 1) + 1;          // +1 block for weff
    k_deg_weff<<<db, 256>>>(src, E, W1, b1, W2, b2);
    k_prep<<<(N + 255) / 256, 256>>>(x, N);

    long groups = ((long)E + 7) / 8;                        // 4 lanes per group
    long sthreads = groups * 4;
    int sblocks = (int)((sthreads + 255) / 256);
    k_scatter<<<sblocks, 256>>>(src, dst, E);

    k_out<<<592, 256>>>(out, N);                            // persistent, 16 nodes/blk-iter
}

// round 8
// speedup vs baseline: 3.0667x; 1.0479x over previous
#include <cuda_runtime.h>

// GCN_75050258530542 — round 8: warp-per-node k_out with register-hoisted
// weights (3 broadcast LDG.128 + 2 coalesced STG per node). Scatter as R6/7.
// out[n,:] = rsqrt(deg_in[n]) * (sum_{e:dst=n} x[src,15:25]*rsqrt(deg_out[src])) @ (W1@W2)
//            + (b1@W2 + b2)

constexpr int NMAX = 100000;
constexpr int FP   = 16;   // 64B rows, 128B-aligned: 4-lane group hits 1 line

__device__ int g_deg_out[NMAX];
__device__ __align__(128) float g_xsn[NMAX * FP];   // slots 0-9 = x[:,15:25]*norm_s; pad 0
__device__ __align__(128) float g_agg[NMAX * FP];   // slots 0-9 sums, slot 10 = deg_in
__device__ float g_Weff[640];                       // W1@W2 (10 x 64)
__device__ float g_beff[64];                        // b1@W2 + b2

// ---------------------------------------------------------------- degrees + weff (last block)
__global__ void k_deg_weff(const int* __restrict__ src, int E,
                           const float* __restrict__ W1, const float* __restrict__ b1,
                           const float* __restrict__ W2, const float* __restrict__ b2) {
    int nb = gridDim.x - 1;
    if ((int)blockIdx.x == nb) {
        for (int idx = threadIdx.x; idx < 704; idx += blockDim.x) {
            if (idx < 640) {
                int i = idx >> 6, j = idx & 63;
                float s = 0.f;
#pragma unroll 8
                for (int k = 0; k < 128; k++) s += W1[i * 128 + k] * W2[k * 64 + j];
                g_Weff[idx] = s;
            } else {
                int j = idx - 640;
                float s = b2[j];
#pragma unroll 8
                for (int k = 0; k < 128; k++) s += b1[k] * W2[k * 64 + j];
                g_beff[j] = s;
            }
        }
        return;
    }
    int n8 = E >> 3;
    int stride = nb * blockDim.x;
    for (int t = blockIdx.x * blockDim.x + threadIdx.x; t < n8; t += stride) {
        int4 s0 = reinterpret_cast<const int4*>(src)[2 * t];
        int4 s1 = reinterpret_cast<const int4*>(src)[2 * t + 1];
        atomicAdd(&g_deg_out[s0.x], 1);
        atomicAdd(&g_deg_out[s0.y], 1);
        atomicAdd(&g_deg_out[s0.z], 1);
        atomicAdd(&g_deg_out[s0.w], 1);
        atomicAdd(&g_deg_out[s1.x], 1);
        atomicAdd(&g_deg_out[s1.y], 1);
        atomicAdd(&g_deg_out[s1.z], 1);
        atomicAdd(&g_deg_out[s1.w], 1);
    }
    if (blockIdx.x == 0 && threadIdx.x == 0) {
        for (int e = (n8 << 3); e < E; e++) atomicAdd(&g_deg_out[src[e]], 1);
    }
}

// ---------------------------------------------------------------- prep: xsn = x[:,15:25]*norm_s
__global__ void k_prep(const float* __restrict__ x, int N) {
    int i = blockIdx.x * blockDim.x + threadIdx.x;
    if (i >= N) return;
    int dout = g_deg_out[i];
    float ns = rsqrtf(dout > 0 ? (float)dout : 1.f);
    const float* base = x + (size_t)i * 40;
    float4 L0 = *reinterpret_cast<const float4*>(base + 12);  // cols 12-15
    float4 L1 = *reinterpret_cast<const float4*>(base + 16);  // cols 16-19
    float4 L2 = *reinterpret_cast<const float4*>(base + 20);  // cols 20-23
    float4 L3 = *reinterpret_cast<const float4*>(base + 24);  // cols 24-27
    float* o = g_xsn + i * FP;
    *reinterpret_cast<float4*>(o)     = make_float4(L0.w * ns, L1.x * ns, L1.y * ns, L1.z * ns); // c15-18
    *reinterpret_cast<float4*>(o + 4) = make_float4(L1.w * ns, L2.x * ns, L2.y * ns, L2.z * ns); // c19-22
    *reinterpret_cast<float4*>(o + 8) = make_float4(L2.w * ns, L3.x * ns, 0.f, 0.f);             // c23-24, pad
}

// ---------------------------------------------------------------- vector RED
__device__ __forceinline__ void red4(float* p, float a, float b, float c, float d) {
    asm volatile("red.global.add.v4.f32 [%0], {%1,%2,%3,%4};"
                 :: "l"(p), "f"(a), "f"(b), "f"(c), "f"(d) : "memory");
}

// ---------------------------------------------------------------- scatter: 4 lanes/edge, 8 edges/group
__global__ void __launch_bounds__(256) k_scatter(const int* __restrict__ src,
                                                 const int* __restrict__ dst, int E) {
    int tid = blockIdx.x * blockDim.x + threadIdx.x;
    int g = tid >> 2;          // edge group (8 edges)
    int q = tid & 3;           // quarter within feature row
    long base = (long)g * 8;
    if (base >= E) return;

    unsigned am = 0xffffffffu;
    int full = (base + 8 <= (long)E);

    int dd[8];
    float4 v[8];
    if (full) {
        int s2a = __ldg(src + base + 2 * q);
        int s2b = __ldg(src + base + 2 * q + 1);
        int d2a = __ldg(dst + base + 2 * q);
        int d2b = __ldg(dst + base + 2 * q + 1);
        int lq = (tid & 31) & ~3;
#pragma unroll
        for (int j = 0; j < 8; j++) {
            int owner = lq + (j >> 1);
            int sj = __shfl_sync(am, (j & 1) ? s2b : s2a, owner);
            dd[j]  = __shfl_sync(am, (j & 1) ? d2b : d2a, owner);
            if (q < 3) v[j] = *reinterpret_cast<const float4*>(g_xsn + (size_t)sj * FP + q * 4);
        }
#pragma unroll
        for (int j = 0; j < 8; j++) {
            if (q < 3) {
                float4 p = v[j];
                if (q == 2) { p.z = 1.0f; p.w = 0.0f; }   // slot 10 += 1 (deg_in)
                red4(g_agg + (size_t)dd[j] * FP + q * 4, p.x, p.y, p.z, p.w);
            }
        }
    } else {
        int cnt = (int)(E - base);
        for (int j = 0; j < cnt; j++) {
            int sj = __ldg(src + base + j);
            int dj = __ldg(dst + base + j);
            if (q < 3) {
                float4 p = *reinterpret_cast<const float4*>(g_xsn + (size_t)sj * FP + q * 4);
                if (q == 2) { p.z = 1.0f; p.w = 0.0f; }
                red4(g_agg + (size_t)dj * FP + q * 4, p.x, p.y, p.z, p.w);
            }
        }
    }
}

// ---------------------------------------------------------------- warp-per-node output matvec
__global__ void __launch_bounds__(256) k_out(float* __restrict__ out, int N) {
    __shared__ float sW[640];
    __shared__ float sb[64];
    int t = threadIdx.x;
    for (int k = t; k < 640; k += 256) sW[k] = g_Weff[k];
    if (t < 64) sb[t] = g_beff[t];
    __syncthreads();

    int lane = t & 31;
    int warp = t >> 5;
    // hoist: lane's weights for output cols lane and lane+32
    float w0[10], w1[10];
#pragma unroll
    for (int k = 0; k < 10; k++) {
        w0[k] = sW[k * 64 + lane];
        w1[k] = sW[k * 64 + 32 + lane];
    }
    float b0 = sb[lane];
    float b1 = sb[lane + 32];

    int step = gridDim.x * 8;
    for (int node = blockIdx.x * 8 + warp; node < N; node += step) {
        const float4* ar = reinterpret_cast<const float4*>(g_agg + (size_t)node * FP);
        float4 a0 = ar[0];   // broadcast within warp: 1 wavefront
        float4 a1 = ar[1];
        float4 a2 = ar[2];   // .z = deg_in
        float cnt = a2.z;
        float nd = rsqrtf(cnt > 0.f ? cnt : 1.f);
        float s0 = a0.x * w0[0] + a0.y * w0[1] + a0.z * w0[2] + a0.w * w0[3]
                 + a1.x * w0[4] + a1.y * w0[5] + a1.z * w0[6] + a1.w * w0[7]
                 + a2.x * w0[8] + a2.y * w0[9];
        float s1 = a0.x * w1[0] + a0.y * w1[1] + a0.z * w1[2] + a0.w * w1[3]
                 + a1.x * w1[4] + a1.y * w1[5] + a1.z * w1[6] + a1.w * w1[7]
                 + a2.x * w1[8] + a2.y * w1[9];
        float* orow = out + (size_t)node * 64;
        orow[lane]      = b0 + nd * s0;
        orow[lane + 32] = b1 + nd * s1;
    }
}

// ---------------------------------------------------------------- launch
extern "C" void kernel_launch(void* const* d_in, const int* in_sizes, int n_in,
                              void* d_out, int out_size) {
    const float* x   = (const float*)d_in[0];
    const int*   src = (const int*)d_in[1];
    const int*   dst = (const int*)d_in[2];
    const float* W1  = (const float*)d_in[3];
    const float* b1  = (const float*)d_in[4];
    const float* W2  = (const float*)d_in[5];
    const float* b2  = (const float*)d_in[6];
    float* out = (float*)d_out;

    int N = in_sizes[0] / 40;
    int E = in_sizes[1];

    void* p_agg = nullptr;
    void* p_deg = nullptr;
    cudaGetSymbolAddress(&p_agg, g_agg);
    cudaGetSymbolAddress(&p_deg, g_deg_out);
    cudaMemsetAsync(p_agg, 0, (size_t)N * FP * sizeof(float));
    cudaMemsetAsync(p_deg, 0, (size_t)N * sizeof(int));

    int n8 = E >> 3;
    int db = (n8 > 0 ? (n8 + 255) / 256 : 1) + 1;          // +1 block for weff
    k_deg_weff<<<db, 256>>>(src, E, W1, b1, W2, b2);
    k_prep<<<(N + 255) / 256, 256>>>(x, N);

    long groups = ((long)E + 7) / 8;                        // 4 lanes per group
    long sthreads = groups * 4;
    int sblocks = (int)((sthreads + 255) / 256);
    k_scatter<<<sblocks, 256>>>(src, dst, E);

    k_out<<<1184, 256>>>(out, N);                           // persistent warp-per-node
}